// round 2
// baseline (speedup 1.0000x reference)
#include <cuda_runtime.h>
#include <math.h>

// Problem constants
#define S_LEN 4096
#define HID_D 2304
#define NH_Q 8
#define N_KV 4
#define HD_H 256
#define SWIN 2048
#define QO_W (NH_Q * HD_H)   // 2048
#define KV_W (N_KV * HD_H)   // 1024

__device__ float g_q [S_LEN * QO_W];
__device__ float g_k [S_LEN * KV_W];
__device__ float g_v [S_LEN * KV_W];
__device__ float g_ao[S_LEN * QO_W];

// ---------------------------------------------------------------------------
// SGEMM: C[M,N] = A[M,K] * B[N,K]^T   (both operands K-major, row-major)
// 128x128 block tile, 8x8 microtile, BK=8, 256 threads, 2 CTAs/SM.
// All dims here are multiples of the tile sizes (no bounds checks).
// ---------------------------------------------------------------------------
__global__ void __launch_bounds__(256, 2) sgemm_nt(
    const float* __restrict__ A, const float* __restrict__ B,
    float* __restrict__ C, int M, int N, int K)
{
    __shared__ float As[8][128];
    __shared__ float Bs[8][128];

    const int tid  = threadIdx.x;
    const int tx   = tid & 15;
    const int ty   = tid >> 4;
    const int lrow = tid >> 1;          // 0..127
    const int lk   = (tid & 1) << 2;    // 0 or 4

    const float* Ag = A + (size_t)(blockIdx.y * 128 + lrow) * K + lk;
    const float* Bg = B + (size_t)(blockIdx.x * 128 + lrow) * K + lk;

    float acc[8][8];
#pragma unroll
    for (int i = 0; i < 8; i++)
#pragma unroll
        for (int j = 0; j < 8; j++) acc[i][j] = 0.f;

    float4 a_reg = *(const float4*)Ag;
    float4 b_reg = *(const float4*)Bg;

    for (int k0 = 0; k0 < K; k0 += 8) {
        As[lk + 0][lrow] = a_reg.x; As[lk + 1][lrow] = a_reg.y;
        As[lk + 2][lrow] = a_reg.z; As[lk + 3][lrow] = a_reg.w;
        Bs[lk + 0][lrow] = b_reg.x; Bs[lk + 1][lrow] = b_reg.y;
        Bs[lk + 2][lrow] = b_reg.z; Bs[lk + 3][lrow] = b_reg.w;
        __syncthreads();
        if (k0 + 8 < K) {
            a_reg = *(const float4*)(Ag + k0 + 8);
            b_reg = *(const float4*)(Bg + k0 + 8);
        }
#pragma unroll
        for (int kk = 0; kk < 8; kk++) {
            float4 a0 = *(const float4*)&As[kk][ty * 4];
            float4 a1 = *(const float4*)&As[kk][64 + ty * 4];
            float4 b0 = *(const float4*)&Bs[kk][tx * 4];
            float4 b1 = *(const float4*)&Bs[kk][64 + tx * 4];
            float av[8] = {a0.x, a0.y, a0.z, a0.w, a1.x, a1.y, a1.z, a1.w};
            float bv[8] = {b0.x, b0.y, b0.z, b0.w, b1.x, b1.y, b1.z, b1.w};
#pragma unroll
            for (int i = 0; i < 8; i++)
#pragma unroll
                for (int j = 0; j < 8; j++)
                    acc[i][j] = fmaf(av[i], bv[j], acc[i][j]);
        }
        __syncthreads();
    }

    const int r0 = blockIdx.y * 128;
    const int c0 = blockIdx.x * 128;
#pragma unroll
    for (int i = 0; i < 8; i++) {
        int r = r0 + ((i < 4) ? (ty * 4 + i) : (64 + ty * 4 + (i - 4)));
        float* Cp = C + (size_t)r * N + c0;
        *(float4*)(Cp + tx * 4)      = make_float4(acc[i][0], acc[i][1], acc[i][2], acc[i][3]);
        *(float4*)(Cp + 64 + tx * 4) = make_float4(acc[i][4], acc[i][5], acc[i][6], acc[i][7]);
    }
}

// ---------------------------------------------------------------------------
// RoPE, in place on q (S x 2048) and k (S x 1024).
// One thread per (row, head, freq-pair).
// ---------------------------------------------------------------------------
__global__ void rope_kernel(float* __restrict__ q, float* __restrict__ k,
                            const int* __restrict__ pos)
{
    const int TQ = S_LEN * NH_Q * 128;
    const int TK = S_LEN * N_KV * 128;
    int i = blockIdx.x * blockDim.x + threadIdx.x;
    if (i >= TQ + TK) return;

    float* base;
    int s, d;
    if (i < TQ) {
        d = i & 127;
        int h = (i >> 7) & 7;
        s = i >> 10;
        base = q + (size_t)s * QO_W + h * HD_H;
    } else {
        int j = i - TQ;
        d = j & 127;
        int h = (j >> 7) & 3;
        s = j >> 9;
        base = k + (size_t)s * KV_W + h * HD_H;
    }
    float p   = (float)pos[s];
    float inv = powf(10000.f, -(float)d * (1.f / 128.f));
    float ang = p * inv;
    float c, sn;
    sincosf(ang, &sn, &c);
    float x1 = base[d];
    float x2 = base[d + 128];
    base[d]       = x1 * c - x2 * sn;
    base[d + 128] = x2 * c + x1 * sn;
}

// ---------------------------------------------------------------------------
// Flash attention, fp32. BM=BN=64, HD=256, 256 threads (16x16 grid).
// Smem layouts chosen for LDS behavior:
//   q4 [64 rows][64 f4]       : compute loads are pure broadcast (no pad)
//   k4/v4 [64 rows][65 f4]    : pad=1 f4 => row stride 65 f4; with the
//                               strided n-map (n = tx + 16*j), float4 loads
//                               hit distinct wide-banks (<=2-way).
//   Ps [64][68] floats        : scores / probabilities.
// Online softmax with softcap(50)*tanh and sliding-window+causal mask.
// ---------------------------------------------------------------------------
#define ATTN_SMEM_FLOATS (64*64*4 + 64*65*4 + 64*65*4 + 64*68 + 64*3 + 64*4)
#define ATTN_SMEM_BYTES  (ATTN_SMEM_FLOATS * 4)

__global__ void __launch_bounds__(256) attn_kernel(
    const float* __restrict__ qg, const float* __restrict__ kg,
    const float* __restrict__ vg, float* __restrict__ outg)
{
    extern __shared__ float sm[];
    float4* q4  = (float4*)sm;            // 64*64 f4
    float4* k4  = q4 + 64 * 64;           // 64*65 f4
    float4* v4  = k4 + 64 * 65;           // 64*65 f4
    float*  Ps  = (float*)(v4 + 64 * 65); // 64*68
    float*  m_s = Ps + 64 * 68;           // 64
    float*  l_s = m_s + 64;               // 64
    float*  sf_s= l_s + 64;               // 64
    float*  red = sf_s + 64;              // 64*4

    const int tid = threadIdx.x;
    const int tx  = tid & 15;
    const int ty  = tid >> 4;
    const int qt  = blockIdx.x;
    const int h   = blockIdx.y;
    const int qs  = qt * 64;
    const int kvh = h >> 1;                     // GQA: 2 q-heads per kv-head
    const float SCALE_F = 0.0625f;              // 256^-0.5
    const float CAP = 50.f, INV_CAP = 1.f / 50.f;

    // Load + pre-scale Q tile (rows qs..qs+63, this head's 256 dims)
    const float* qbase = qg + (size_t)qs * QO_W + h * HD_H;
#pragma unroll
    for (int it = 0; it < 16; it++) {
        int idx = tid + it * 256;
        int r = idx >> 6, d4 = idx & 63;
        float4 val = *(const float4*)(qbase + (size_t)r * QO_W + d4 * 4);
        val.x *= SCALE_F; val.y *= SCALE_F; val.z *= SCALE_F; val.w *= SCALE_F;
        q4[r * 64 + d4] = val;
    }
    if (tid < 64) { m_s[tid] = -1e30f; l_s[tid] = 0.f; }

    // Output accumulator: rows ty*4+i, float4 column-quads at (tx + 16*jj)
    float o[4][16];
#pragma unroll
    for (int i = 0; i < 4; i++)
#pragma unroll
        for (int c = 0; c < 16; c++) o[i][c] = 0.f;

    const int kt_lo = (qs - (SWIN - 1) > 0 ? qs - (SWIN - 1) : 0) >> 6;

    for (int kt = kt_lo; kt <= qt; kt++) {
        const int ks0 = kt * 64;
        __syncthreads();   // previous PV done before K/V (and Q on iter 0) reuse
        const float* kbase = kg + (size_t)ks0 * KV_W + kvh * HD_H;
        const float* vbase = vg + (size_t)ks0 * KV_W + kvh * HD_H;
#pragma unroll
        for (int it = 0; it < 16; it++) {
            int idx = tid + it * 256;
            int r = idx >> 6, d4 = idx & 63;
            k4[r * 65 + d4] = *(const float4*)(kbase + (size_t)r * KV_W + d4 * 4);
            v4[r * 65 + d4] = *(const float4*)(vbase + (size_t)r * KV_W + d4 * 4);
        }
        __syncthreads();

        // ---- S = Q K^T (pre-scaled), 4x4 microtile, n = tx + 16*j ----
        float s[4][4];
#pragma unroll
        for (int i = 0; i < 4; i++)
#pragma unroll
            for (int j = 0; j < 4; j++) s[i][j] = 0.f;

#pragma unroll 2
        for (int d4 = 0; d4 < 64; d4++) {
            float4 qa[4], kb[4];
#pragma unroll
            for (int i = 0; i < 4; i++) qa[i] = q4[(ty * 4 + i) * 64 + d4];
#pragma unroll
            for (int j = 0; j < 4; j++) kb[j] = k4[(tx + 16 * j) * 65 + d4];
#pragma unroll
            for (int i = 0; i < 4; i++)
#pragma unroll
                for (int j = 0; j < 4; j++) {
                    s[i][j] = fmaf(qa[i].x, kb[j].x, s[i][j]);
                    s[i][j] = fmaf(qa[i].y, kb[j].y, s[i][j]);
                    s[i][j] = fmaf(qa[i].z, kb[j].z, s[i][j]);
                    s[i][j] = fmaf(qa[i].w, kb[j].w, s[i][j]);
                }
        }

        // ---- softcap, then mask, store to Ps ----
#pragma unroll
        for (int i = 0; i < 4; i++)
#pragma unroll
            for (int j = 0; j < 4; j++) {
                float sv = CAP * tanhf(s[i][j] * INV_CAP);
                int gi = qs + ty * 4 + i;
                int gj = ks0 + tx + 16 * j;
                bool ok = (gj <= gi) && ((gi - gj) < SWIN);
                Ps[(ty * 4 + i) * 68 + tx + 16 * j] = ok ? sv : -1e30f;
            }
        __syncthreads();

        // ---- row max (4 threads per row) ----
        {
            int row = tid >> 2, l4 = tid & 3;
            const float* pr = Ps + row * 68 + l4 * 16;
            float mx = -1e30f;
#pragma unroll
            for (int t = 0; t < 16; t++) mx = fmaxf(mx, pr[t]);
            red[row * 4 + l4] = mx;
        }
        __syncthreads();
        if (tid < 64) {
            float mt = fmaxf(fmaxf(red[tid * 4], red[tid * 4 + 1]),
                             fmaxf(red[tid * 4 + 2], red[tid * 4 + 3]));
            float mo = m_s[tid];
            float mn = fmaxf(mo, mt);
            sf_s[tid] = expf(mo - mn);
            m_s[tid]  = mn;
        }
        __syncthreads();

        // ---- exponentiate + partial row sums ----
        {
            int row = tid >> 2, l4 = tid & 3;
            float mn = m_s[row];
            float* pr = Ps + row * 68 + l4 * 16;
            float sum = 0.f;
#pragma unroll
            for (int t = 0; t < 16; t++) {
                float pv = pr[t];
                float e = (pv < -1e29f) ? 0.f : expf(pv - mn);
                pr[t] = e;
                sum += e;
            }
            red[row * 4 + l4] = sum;
        }
        __syncthreads();
        if (tid < 64) {
            l_s[tid] = l_s[tid] * sf_s[tid] +
                       (red[tid * 4] + red[tid * 4 + 1] +
                        red[tid * 4 + 2] + red[tid * 4 + 3]);
        }
        __syncthreads();

        // ---- rescale accumulator ----
#pragma unroll
        for (int i = 0; i < 4; i++) {
            float sf = sf_s[ty * 4 + i];
#pragma unroll
            for (int c = 0; c < 16; c++) o[i][c] *= sf;
        }

        // ---- O += P V ----
#pragma unroll 2
        for (int n = 0; n < 64; n++) {
            float pa[4];
#pragma unroll
            for (int i = 0; i < 4; i++) pa[i] = Ps[(ty * 4 + i) * 68 + n];
            float4 vb[4];
#pragma unroll
            for (int jj = 0; jj < 4; jj++) vb[jj] = v4[n * 65 + tx + 16 * jj];
#pragma unroll
            for (int i = 0; i < 4; i++)
#pragma unroll
                for (int jj = 0; jj < 4; jj++) {
                    o[i][jj * 4 + 0] = fmaf(pa[i], vb[jj].x, o[i][jj * 4 + 0]);
                    o[i][jj * 4 + 1] = fmaf(pa[i], vb[jj].y, o[i][jj * 4 + 1]);
                    o[i][jj * 4 + 2] = fmaf(pa[i], vb[jj].z, o[i][jj * 4 + 2]);
                    o[i][jj * 4 + 3] = fmaf(pa[i], vb[jj].w, o[i][jj * 4 + 3]);
                }
        }
    }

    // ---- normalize + write out (layout [s][h*256 + d]) ----
#pragma unroll
    for (int i = 0; i < 4; i++) {
        int r = ty * 4 + i;
        float inv = 1.f / l_s[r];
        float* op = outg + (size_t)(qs + r) * QO_W + h * HD_H;
#pragma unroll
        for (int jj = 0; jj < 4; jj++) {
            float4 res = make_float4(o[i][jj * 4 + 0] * inv, o[i][jj * 4 + 1] * inv,
                                     o[i][jj * 4 + 2] * inv, o[i][jj * 4 + 3] * inv);
            *(float4*)(op + (tx + 16 * jj) * 4) = res;
        }
    }
}

// ---------------------------------------------------------------------------
// Launch
// ---------------------------------------------------------------------------
extern "C" void kernel_launch(void* const* d_in, const int* in_sizes, int n_in,
                              void* d_out, int out_size)
{
    const float* x   = (const float*)d_in[0];   // [4096, 2304]
    const int*   pos = (const int*)  d_in[1];   // [1, 4096]
    const float* Wq  = (const float*)d_in[2];   // [2048, 2304]
    const float* Wk  = (const float*)d_in[3];   // [1024, 2304]
    const float* Wv  = (const float*)d_in[4];   // [1024, 2304]
    const float* Wo  = (const float*)d_in[5];   // [2304, 2048]
    float* out = (float*)d_out;                 // [4096, 2304]

    float *gq, *gk, *gv, *gao;
    cudaGetSymbolAddress((void**)&gq,  g_q);
    cudaGetSymbolAddress((void**)&gk,  g_k);
    cudaGetSymbolAddress((void**)&gv,  g_v);
    cudaGetSymbolAddress((void**)&gao, g_ao);

    // QKV projections: C = A * W^T
    sgemm_nt<<<dim3(QO_W / 128, S_LEN / 128), 256>>>(x, Wq, gq, S_LEN, QO_W, HID_D);
    sgemm_nt<<<dim3(KV_W / 128, S_LEN / 128), 256>>>(x, Wk, gk, S_LEN, KV_W, HID_D);
    sgemm_nt<<<dim3(KV_W / 128, S_LEN / 128), 256>>>(x, Wv, gv, S_LEN, KV_W, HID_D);

    // RoPE in place on q and k
    {
        int total = S_LEN * (NH_Q + N_KV) * 128;
        rope_kernel<<<(total + 255) / 256, 256>>>(gq, gk, pos);
    }

    // Flash attention
    cudaFuncSetAttribute(attn_kernel, cudaFuncAttributeMaxDynamicSharedMemorySize,
                         ATTN_SMEM_BYTES);
    attn_kernel<<<dim3(S_LEN / 64, NH_Q), 256, ATTN_SMEM_BYTES>>>(gq, gk, gv, gao);

    // Output projection: out = AO * Wo^T
    sgemm_nt<<<dim3(HID_D / 128, S_LEN / 128), 256>>>(gao, Wo, out, S_LEN, HID_D, QO_W);
}

// round 5
// speedup vs baseline: 1.4644x; 1.4644x over previous
#include <cuda_runtime.h>
#include <math.h>
#include <stdint.h>

// Problem constants
#define S_LEN 4096
#define HID_D 2304
#define NH_Q 8
#define N_KV 4
#define HD_H 256
#define SWIN 2048
#define QO_W (NH_Q * HD_H)   // 2048
#define KV_W (N_KV * HD_H)   // 1024

__device__ float g_q [S_LEN * QO_W];
__device__ float g_k [S_LEN * KV_W];
__device__ float g_v [S_LEN * KV_W];
__device__ float g_ao[S_LEN * QO_W];

// ===========================================================================
// helpers
// ===========================================================================
__device__ __forceinline__ uint32_t smem_u32(const void* p) {
    uint32_t a;
    asm("{ .reg .u64 t; cvta.to.shared.u64 t, %1; cvt.u32.u64 %0, t; }" : "=r"(a) : "l"(p));
    return a;
}

__device__ __forceinline__ uint32_t pack_bf16_rn(float lo, float hi) {
    uint32_t r;
    asm("cvt.rn.bf16x2.f32 %0, %1, %2;" : "=r"(r) : "f"(hi), "f"(lo));
    return r;
}

// convert one float4 into hi(trunc)/lo(residual, rn) bf16 quads, store 8B each
__device__ __forceinline__ void cvt_store(uint32_t dst_hi, uint32_t dst_lo, float4 v) {
    uint32_t bx = __float_as_uint(v.x), by = __float_as_uint(v.y);
    uint32_t bz = __float_as_uint(v.z), bw = __float_as_uint(v.w);
    uint32_t h0 = __byte_perm(bx, by, 0x7632);
    uint32_t h1 = __byte_perm(bz, bw, 0x7632);
    float lx = v.x - __uint_as_float(bx & 0xFFFF0000u);
    float ly = v.y - __uint_as_float(by & 0xFFFF0000u);
    float lz = v.z - __uint_as_float(bz & 0xFFFF0000u);
    float lw = v.w - __uint_as_float(bw & 0xFFFF0000u);
    uint32_t l0 = pack_bf16_rn(lx, ly);
    uint32_t l1 = pack_bf16_rn(lz, lw);
    asm volatile("st.shared.v2.b32 [%0], {%1,%2};" :: "r"(dst_hi), "r"(h0), "r"(h1) : "memory");
    asm volatile("st.shared.v2.b32 [%0], {%1,%2};" :: "r"(dst_lo), "r"(l0), "r"(l1) : "memory");
}

#define LDSM4(R0, R1, R2, R3, ADDR) \
    asm volatile("ldmatrix.sync.aligned.m8n8.x4.shared.b16 {%0,%1,%2,%3}, [%4];" \
        : "=r"(R0), "=r"(R1), "=r"(R2), "=r"(R3) : "r"(ADDR))

#define MMA16816(CC, A0, A1, A2, A3, B0, B1) \
    asm volatile("mma.sync.aligned.m16n8k16.row.col.f32.bf16.bf16.f32 " \
        "{%0,%1,%2,%3}, {%4,%5,%6,%7}, {%8,%9}, {%0,%1,%2,%3};" \
        : "+f"((CC)[0]), "+f"((CC)[1]), "+f"((CC)[2]), "+f"((CC)[3]) \
        : "r"(A0), "r"(A1), "r"(A2), "r"(A3), "r"(B0), "r"(B1))

// ===========================================================================
// HMMA GEMM: C[M,N] = A[M,K] * B[N,K]^T  (fp32 in/out, bf16x3 internally)
// 128x128 CTA tile, BK=32, 256 threads (8 warps, each 64x32).
// Smem tiles [128 rows][32 bf16] = 64B rows, xor swizzle on 16B chunks:
//   phys_chunk = chunk ^ ((row>>1)&3)  -> conflict-free ldmatrix + STS.
// ===========================================================================
#define GBK 32

__global__ void __launch_bounds__(256) gemm_mma(
    const float* __restrict__ A, const float* __restrict__ B,
    float* __restrict__ C, int N, int K)
{
    __shared__ __align__(1024) unsigned char sm_raw[4 * 8192];
    const uint32_t sbase = smem_u32(sm_raw);
    const uint32_t sAh = sbase;
    const uint32_t sAl = sbase + 8192;
    const uint32_t sBh = sbase + 16384;
    const uint32_t sBl = sbase + 24576;

    const int tid  = threadIdx.x;
    const int wid  = tid >> 5;
    const int lane = tid & 31;
    const int wm   = (wid >> 2) * 64;   // warp row base in tile
    const int wn   = (wid & 3) * 32;    // warp col base in tile
    const int m0   = blockIdx.y * 128;
    const int n0   = blockIdx.x * 128;
    const int NI   = K / GBK;

    float acc[4][4][4];
#pragma unroll
    for (int mt = 0; mt < 4; mt++)
#pragma unroll
        for (int nt = 0; nt < 4; nt++)
#pragma unroll
            for (int q = 0; q < 4; q++) acc[mt][nt][q] = 0.f;

    // per-lane ldmatrix addressing components
    const int a_r = (lane & 7) + ((lane >> 3) & 1) * 8;  // A: bit3 -> +8 rows
    const int a_c = (lane >> 4) & 1;                     // A: bit4 -> +8 k (chunk+1)
    const int b_r = (lane & 7) + ((lane >> 4) & 1) * 8;  // B: bit4 -> +8 rows (n)
    const int b_c = (lane >> 3) & 1;                     // B: bit3 -> +8 k

    float4 stA[4], stB[4];

    auto load_stage = [&](int k0) {
#pragma unroll
        for (int i = 0; i < 4; i++) {
            int idx = tid + i * 256;
            int r = idx >> 3, c4 = idx & 7;
            stA[i] = *(const float4*)(A + (size_t)(m0 + r) * K + k0 + c4 * 4);
            stB[i] = *(const float4*)(B + (size_t)(n0 + r) * K + k0 + c4 * 4);
        }
    };
    auto store_stage = [&]() {
#pragma unroll
        for (int i = 0; i < 4; i++) {
            int idx = tid + i * 256;
            int r = idx >> 3, c4 = idx & 7;
            uint32_t off = r * 64 + ((((c4 >> 1)) ^ ((r >> 1) & 3)) << 4) + (c4 & 1) * 8;
            cvt_store(sAh + off, sAl + off, stA[i]);
            cvt_store(sBh + off, sBl + off, stB[i]);
        }
    };

    load_stage(0);

    for (int it = 0; it < NI; it++) {
        __syncthreads();           // smem free (prev compute done)
        store_stage();
        __syncthreads();           // smem ready
        if (it + 1 < NI) load_stage((it + 1) * GBK);

#pragma unroll
        for (int ks = 0; ks < 2; ks++) {
            const int cb = ks * 2;   // chunk base for this k16
            uint32_t ah[4][4], bh[4][2], bl[4][2];

            // A-hi fragments (4 m-tiles)
#pragma unroll
            for (int mt = 0; mt < 4; mt++) {
                int r = wm + mt * 16 + a_r;
                uint32_t ad = sAh + r * 64 + (((cb + a_c) ^ ((r >> 1) & 3)) << 4);
                LDSM4(ah[mt][0], ah[mt][1], ah[mt][2], ah[mt][3], ad);
            }
            // B-hi fragments (4 n-tiles, packed 2-per-x4)
#pragma unroll
            for (int np = 0; np < 2; np++) {
                int r = wn + np * 16 + b_r;
                uint32_t bd = sBh + r * 64 + (((cb + b_c) ^ ((r >> 1) & 3)) << 4);
                LDSM4(bh[2 * np][0], bh[2 * np][1], bh[2 * np + 1][0], bh[2 * np + 1][1], bd);
            }
            // hi * hi
#pragma unroll
            for (int mt = 0; mt < 4; mt++)
#pragma unroll
                for (int nt = 0; nt < 4; nt++)
                    MMA16816(acc[mt][nt], ah[mt][0], ah[mt][1], ah[mt][2], ah[mt][3],
                             bh[nt][0], bh[nt][1]);
            // B-lo fragments
#pragma unroll
            for (int np = 0; np < 2; np++) {
                int r = wn + np * 16 + b_r;
                uint32_t bd = sBl + r * 64 + (((cb + b_c) ^ ((r >> 1) & 3)) << 4);
                LDSM4(bl[2 * np][0], bl[2 * np][1], bl[2 * np + 1][0], bl[2 * np + 1][1], bd);
            }
            // hi * lo
#pragma unroll
            for (int mt = 0; mt < 4; mt++)
#pragma unroll
                for (int nt = 0; nt < 4; nt++)
                    MMA16816(acc[mt][nt], ah[mt][0], ah[mt][1], ah[mt][2], ah[mt][3],
                             bl[nt][0], bl[nt][1]);
            // A-lo fragments (reuse ah regs)
#pragma unroll
            for (int mt = 0; mt < 4; mt++) {
                int r = wm + mt * 16 + a_r;
                uint32_t ad = sAl + r * 64 + (((cb + a_c) ^ ((r >> 1) & 3)) << 4);
                LDSM4(ah[mt][0], ah[mt][1], ah[mt][2], ah[mt][3], ad);
            }
            // lo * hi
#pragma unroll
            for (int mt = 0; mt < 4; mt++)
#pragma unroll
                for (int nt = 0; nt < 4; nt++)
                    MMA16816(acc[mt][nt], ah[mt][0], ah[mt][1], ah[mt][2], ah[mt][3],
                             bh[nt][0], bh[nt][1]);
        }
    }

    // epilogue: direct fp32 stores (fragment layout: row lr(+8), cols lc,lc+1)
    const int lr = lane >> 2;
    const int lc = (lane & 3) * 2;
#pragma unroll
    for (int mt = 0; mt < 4; mt++) {
#pragma unroll
        for (int nt = 0; nt < 4; nt++) {
            float* p = C + (size_t)(m0 + wm + mt * 16 + lr) * N + n0 + wn + nt * 8 + lc;
            *(float2*)p             = make_float2(acc[mt][nt][0], acc[mt][nt][1]);
            *(float2*)(p + 8 * N)   = make_float2(acc[mt][nt][2], acc[mt][nt][3]);
        }
    }
}

// ---------------------------------------------------------------------------
// RoPE, in place on q (S x 2048) and k (S x 1024).
// ---------------------------------------------------------------------------
__global__ void rope_kernel(float* __restrict__ q, float* __restrict__ k,
                            const int* __restrict__ pos)
{
    const int TQ = S_LEN * NH_Q * 128;
    const int TK = S_LEN * N_KV * 128;
    int i = blockIdx.x * blockDim.x + threadIdx.x;
    if (i >= TQ + TK) return;

    float* base;
    int s, d;
    if (i < TQ) {
        d = i & 127;
        int h = (i >> 7) & 7;
        s = i >> 10;
        base = q + (size_t)s * QO_W + h * HD_H;
    } else {
        int j = i - TQ;
        d = j & 127;
        int h = (j >> 7) & 3;
        s = j >> 9;
        base = k + (size_t)s * KV_W + h * HD_H;
    }
    float p   = (float)pos[s];
    float inv = powf(10000.f, -(float)d * (1.f / 128.f));
    float ang = p * inv;
    float c, sn;
    sincosf(ang, &sn, &c);
    float x1 = base[d];
    float x2 = base[d + 128];
    base[d]       = x1 * c - x2 * sn;
    base[d + 128] = x2 * c + x1 * sn;
}

// ---------------------------------------------------------------------------
// Flash attention, fp32 SIMT (unchanged).
// ---------------------------------------------------------------------------
#define ATTN_SMEM_FLOATS (64*64*4 + 64*65*4 + 64*65*4 + 64*68 + 64*3 + 64*4)
#define ATTN_SMEM_BYTES  (ATTN_SMEM_FLOATS * 4)

__global__ void __launch_bounds__(256) attn_kernel(
    const float* __restrict__ qg, const float* __restrict__ kg,
    const float* __restrict__ vg, float* __restrict__ outg)
{
    extern __shared__ float sm[];
    float4* q4  = (float4*)sm;
    float4* k4  = q4 + 64 * 64;
    float4* v4  = k4 + 64 * 65;
    float*  Ps  = (float*)(v4 + 64 * 65);
    float*  m_s = Ps + 64 * 68;
    float*  l_s = m_s + 64;
    float*  sf_s= l_s + 64;
    float*  red = sf_s + 64;

    const int tid = threadIdx.x;
    const int tx  = tid & 15;
    const int ty  = tid >> 4;
    const int qt  = blockIdx.x;
    const int h   = blockIdx.y;
    const int qs  = qt * 64;
    const int kvh = h >> 1;
    const float SCALE_F = 0.0625f;
    const float CAP = 50.f, INV_CAP = 1.f / 50.f;

    const float* qbase = qg + (size_t)qs * QO_W + h * HD_H;
#pragma unroll
    for (int it = 0; it < 16; it++) {
        int idx = tid + it * 256;
        int r = idx >> 6, d4 = idx & 63;
        float4 val = *(const float4*)(qbase + (size_t)r * QO_W + d4 * 4);
        val.x *= SCALE_F; val.y *= SCALE_F; val.z *= SCALE_F; val.w *= SCALE_F;
        q4[r * 64 + d4] = val;
    }
    if (tid < 64) { m_s[tid] = -1e30f; l_s[tid] = 0.f; }

    float o[4][16];
#pragma unroll
    for (int i = 0; i < 4; i++)
#pragma unroll
        for (int c = 0; c < 16; c++) o[i][c] = 0.f;

    const int kt_lo = (qs - (SWIN - 1) > 0 ? qs - (SWIN - 1) : 0) >> 6;

    for (int kt = kt_lo; kt <= qt; kt++) {
        const int ks0 = kt * 64;
        __syncthreads();
        const float* kbase = kg + (size_t)ks0 * KV_W + kvh * HD_H;
        const float* vbase = vg + (size_t)ks0 * KV_W + kvh * HD_H;
#pragma unroll
        for (int it = 0; it < 16; it++) {
            int idx = tid + it * 256;
            int r = idx >> 6, d4 = idx & 63;
            k4[r * 65 + d4] = *(const float4*)(kbase + (size_t)r * KV_W + d4 * 4);
            v4[r * 65 + d4] = *(const float4*)(vbase + (size_t)r * KV_W + d4 * 4);
        }
        __syncthreads();

        float s[4][4];
#pragma unroll
        for (int i = 0; i < 4; i++)
#pragma unroll
            for (int j = 0; j < 4; j++) s[i][j] = 0.f;

#pragma unroll 2
        for (int d4 = 0; d4 < 64; d4++) {
            float4 qa[4], kb[4];
#pragma unroll
            for (int i = 0; i < 4; i++) qa[i] = q4[(ty * 4 + i) * 64 + d4];
#pragma unroll
            for (int j = 0; j < 4; j++) kb[j] = k4[(tx + 16 * j) * 65 + d4];
#pragma unroll
            for (int i = 0; i < 4; i++)
#pragma unroll
                for (int j = 0; j < 4; j++) {
                    s[i][j] = fmaf(qa[i].x, kb[j].x, s[i][j]);
                    s[i][j] = fmaf(qa[i].y, kb[j].y, s[i][j]);
                    s[i][j] = fmaf(qa[i].z, kb[j].z, s[i][j]);
                    s[i][j] = fmaf(qa[i].w, kb[j].w, s[i][j]);
                }
        }

#pragma unroll
        for (int i = 0; i < 4; i++)
#pragma unroll
            for (int j = 0; j < 4; j++) {
                float sv = CAP * tanhf(s[i][j] * INV_CAP);
                int gi = qs + ty * 4 + i;
                int gj = ks0 + tx + 16 * j;
                bool ok = (gj <= gi) && ((gi - gj) < SWIN);
                Ps[(ty * 4 + i) * 68 + tx + 16 * j] = ok ? sv : -1e30f;
            }
        __syncthreads();

        {
            int row = tid >> 2, l4 = tid & 3;
            const float* pr = Ps + row * 68 + l4 * 16;
            float mx = -1e30f;
#pragma unroll
            for (int t = 0; t < 16; t++) mx = fmaxf(mx, pr[t]);
            red[row * 4 + l4] = mx;
        }
        __syncthreads();
        if (tid < 64) {
            float mt = fmaxf(fmaxf(red[tid * 4], red[tid * 4 + 1]),
                             fmaxf(red[tid * 4 + 2], red[tid * 4 + 3]));
            float mo = m_s[tid];
            float mn = fmaxf(mo, mt);
            sf_s[tid] = expf(mo - mn);
            m_s[tid]  = mn;
        }
        __syncthreads();

        {
            int row = tid >> 2, l4 = tid & 3;
            float mn = m_s[row];
            float* pr = Ps + row * 68 + l4 * 16;
            float sum = 0.f;
#pragma unroll
            for (int t = 0; t < 16; t++) {
                float pv = pr[t];
                float e = (pv < -1e29f) ? 0.f : expf(pv - mn);
                pr[t] = e;
                sum += e;
            }
            red[row * 4 + l4] = sum;
        }
        __syncthreads();
        if (tid < 64) {
            l_s[tid] = l_s[tid] * sf_s[tid] +
                       (red[tid * 4] + red[tid * 4 + 1] +
                        red[tid * 4 + 2] + red[tid * 4 + 3]);
        }
        __syncthreads();

#pragma unroll
        for (int i = 0; i < 4; i++) {
            float sf = sf_s[ty * 4 + i];
#pragma unroll
            for (int c = 0; c < 16; c++) o[i][c] *= sf;
        }

#pragma unroll 2
        for (int n = 0; n < 64; n++) {
            float pa[4];
#pragma unroll
            for (int i = 0; i < 4; i++) pa[i] = Ps[(ty * 4 + i) * 68 + n];
            float4 vb[4];
#pragma unroll
            for (int jj = 0; jj < 4; jj++) vb[jj] = v4[n * 65 + tx + 16 * jj];
#pragma unroll
            for (int i = 0; i < 4; i++)
#pragma unroll
                for (int jj = 0; jj < 4; jj++) {
                    o[i][jj * 4 + 0] = fmaf(pa[i], vb[jj].x, o[i][jj * 4 + 0]);
                    o[i][jj * 4 + 1] = fmaf(pa[i], vb[jj].y, o[i][jj * 4 + 1]);
                    o[i][jj * 4 + 2] = fmaf(pa[i], vb[jj].z, o[i][jj * 4 + 2]);
                    o[i][jj * 4 + 3] = fmaf(pa[i], vb[jj].w, o[i][jj * 4 + 3]);
                }
        }
    }

#pragma unroll
    for (int i = 0; i < 4; i++) {
        int r = ty * 4 + i;
        float inv = 1.f / l_s[r];
        float* op = outg + (size_t)(qs + r) * QO_W + h * HD_H;
#pragma unroll
        for (int jj = 0; jj < 4; jj++) {
            float4 res = make_float4(o[i][jj * 4 + 0] * inv, o[i][jj * 4 + 1] * inv,
                                     o[i][jj * 4 + 2] * inv, o[i][jj * 4 + 3] * inv);
            *(float4*)(op + (tx + 16 * jj) * 4) = res;
        }
    }
}

// ---------------------------------------------------------------------------
// Launch
// ---------------------------------------------------------------------------
extern "C" void kernel_launch(void* const* d_in, const int* in_sizes, int n_in,
                              void* d_out, int out_size)
{
    const float* x   = (const float*)d_in[0];   // [4096, 2304]
    const int*   pos = (const int*)  d_in[1];   // [1, 4096]
    const float* Wq  = (const float*)d_in[2];   // [2048, 2304]
    const float* Wk  = (const float*)d_in[3];   // [1024, 2304]
    const float* Wv  = (const float*)d_in[4];   // [1024, 2304]
    const float* Wo  = (const float*)d_in[5];   // [2304, 2048]
    float* out = (float*)d_out;                 // [4096, 2304]

    float *gq, *gk, *gv, *gao;
    cudaGetSymbolAddress((void**)&gq,  g_q);
    cudaGetSymbolAddress((void**)&gk,  g_k);
    cudaGetSymbolAddress((void**)&gv,  g_v);
    cudaGetSymbolAddress((void**)&gao, g_ao);

    cudaFuncSetAttribute(attn_kernel, cudaFuncAttributeMaxDynamicSharedMemorySize,
                         ATTN_SMEM_BYTES);

    // QKV projections on HMMA (bf16x3 split): C = A * W^T
    gemm_mma<<<dim3(QO_W / 128, S_LEN / 128), 256>>>(x, Wq, gq, QO_W, HID_D);
    gemm_mma<<<dim3(KV_W / 128, S_LEN / 128), 256>>>(x, Wk, gk, KV_W, HID_D);
    gemm_mma<<<dim3(KV_W / 128, S_LEN / 128), 256>>>(x, Wv, gv, KV_W, HID_D);

    // RoPE in place on q and k
    {
        int total = S_LEN * (NH_Q + N_KV) * 128;
        rope_kernel<<<(total + 255) / 256, 256>>>(gq, gk, pos);
    }

    // Flash attention (fp32 SIMT)
    attn_kernel<<<dim3(S_LEN / 64, NH_Q), 256, ATTN_SMEM_BYTES>>>(gq, gk, gv, gao);

    // Output projection: out = AO * Wo^T
    gemm_mma<<<dim3(HID_D / 128, S_LEN / 128), 256>>>(gao, Wo, out, HID_D, QO_W);
}

// round 6
// speedup vs baseline: 2.4345x; 1.6625x over previous
#include <cuda_runtime.h>
#include <math.h>
#include <stdint.h>

// Problem constants
#define S_LEN 4096
#define HID_D 2304
#define NH_Q 8
#define N_KV 4
#define HD_H 256
#define SWIN 2048
#define QO_W (NH_Q * HD_H)   // 2048
#define KV_W (N_KV * HD_H)   // 1024

__device__ float g_q [S_LEN * QO_W];
__device__ float g_k [S_LEN * KV_W];
__device__ float g_v [S_LEN * KV_W];
__device__ float g_ao[S_LEN * QO_W];

// ===========================================================================
// helpers
// ===========================================================================
__device__ __forceinline__ uint32_t smem_u32(const void* p) {
    uint32_t a;
    asm("{ .reg .u64 t; cvta.to.shared.u64 t, %1; cvt.u32.u64 %0, t; }" : "=r"(a) : "l"(p));
    return a;
}

__device__ __forceinline__ uint32_t pack_bf16_rn(float lo, float hi) {
    uint32_t r;
    asm("cvt.rn.bf16x2.f32 %0, %1, %2;" : "=r"(r) : "f"(hi), "f"(lo));
    return r;
}

// convert one float4 into hi(trunc)/lo(residual, rn) bf16 quads, store 8B each
__device__ __forceinline__ void cvt_store(uint32_t dst_hi, uint32_t dst_lo, float4 v) {
    uint32_t bx = __float_as_uint(v.x), by = __float_as_uint(v.y);
    uint32_t bz = __float_as_uint(v.z), bw = __float_as_uint(v.w);
    uint32_t h0 = __byte_perm(bx, by, 0x7632);
    uint32_t h1 = __byte_perm(bz, bw, 0x7632);
    float lx = v.x - __uint_as_float(bx & 0xFFFF0000u);
    float ly = v.y - __uint_as_float(by & 0xFFFF0000u);
    float lz = v.z - __uint_as_float(bz & 0xFFFF0000u);
    float lw = v.w - __uint_as_float(bw & 0xFFFF0000u);
    uint32_t l0 = pack_bf16_rn(lx, ly);
    uint32_t l1 = pack_bf16_rn(lz, lw);
    asm volatile("st.shared.v2.b32 [%0], {%1,%2};" :: "r"(dst_hi), "r"(h0), "r"(h1) : "memory");
    asm volatile("st.shared.v2.b32 [%0], {%1,%2};" :: "r"(dst_lo), "r"(l0), "r"(l1) : "memory");
}

#define LDSM4(R0, R1, R2, R3, ADDR) \
    asm volatile("ldmatrix.sync.aligned.m8n8.x4.shared.b16 {%0,%1,%2,%3}, [%4];" \
        : "=r"(R0), "=r"(R1), "=r"(R2), "=r"(R3) : "r"(ADDR))

#define LDSM4T(R0, R1, R2, R3, ADDR) \
    asm volatile("ldmatrix.sync.aligned.m8n8.x4.trans.shared.b16 {%0,%1,%2,%3}, [%4];" \
        : "=r"(R0), "=r"(R1), "=r"(R2), "=r"(R3) : "r"(ADDR))

#define MMA16816(CC, A0, A1, A2, A3, B0, B1) \
    asm volatile("mma.sync.aligned.m16n8k16.row.col.f32.bf16.bf16.f32 " \
        "{%0,%1,%2,%3}, {%4,%5,%6,%7}, {%8,%9}, {%0,%1,%2,%3};" \
        : "+f"((CC)[0]), "+f"((CC)[1]), "+f"((CC)[2]), "+f"((CC)[3]) \
        : "r"(A0), "r"(A1), "r"(A2), "r"(A3), "r"(B0), "r"(B1))

// ===========================================================================
// HMMA GEMM: C[M,N] = A[M,K] * B[N,K]^T  (fp32 in/out, bf16x3 internally)
// ===========================================================================
#define GBK 32

__global__ void __launch_bounds__(256) gemm_mma(
    const float* __restrict__ A, const float* __restrict__ B,
    float* __restrict__ C, int N, int K)
{
    __shared__ __align__(1024) unsigned char sm_raw[4 * 8192];
    const uint32_t sbase = smem_u32(sm_raw);
    const uint32_t sAh = sbase;
    const uint32_t sAl = sbase + 8192;
    const uint32_t sBh = sbase + 16384;
    const uint32_t sBl = sbase + 24576;

    const int tid  = threadIdx.x;
    const int wid  = tid >> 5;
    const int lane = tid & 31;
    const int wm   = (wid >> 2) * 64;
    const int wn   = (wid & 3) * 32;
    const int m0   = blockIdx.y * 128;
    const int n0   = blockIdx.x * 128;
    const int NI   = K / GBK;

    float acc[4][4][4];
#pragma unroll
    for (int mt = 0; mt < 4; mt++)
#pragma unroll
        for (int nt = 0; nt < 4; nt++)
#pragma unroll
            for (int q = 0; q < 4; q++) acc[mt][nt][q] = 0.f;

    const int a_r = (lane & 7) + ((lane >> 3) & 1) * 8;
    const int a_c = (lane >> 4) & 1;
    const int b_r = (lane & 7) + ((lane >> 4) & 1) * 8;
    const int b_c = (lane >> 3) & 1;

    float4 stA[4], stB[4];

    auto load_stage = [&](int k0) {
#pragma unroll
        for (int i = 0; i < 4; i++) {
            int idx = tid + i * 256;
            int r = idx >> 3, c4 = idx & 7;
            stA[i] = *(const float4*)(A + (size_t)(m0 + r) * K + k0 + c4 * 4);
            stB[i] = *(const float4*)(B + (size_t)(n0 + r) * K + k0 + c4 * 4);
        }
    };
    auto store_stage = [&]() {
#pragma unroll
        for (int i = 0; i < 4; i++) {
            int idx = tid + i * 256;
            int r = idx >> 3, c4 = idx & 7;
            uint32_t off = r * 64 + ((((c4 >> 1)) ^ ((r >> 1) & 3)) << 4) + (c4 & 1) * 8;
            cvt_store(sAh + off, sAl + off, stA[i]);
            cvt_store(sBh + off, sBl + off, stB[i]);
        }
    };

    load_stage(0);

    for (int it = 0; it < NI; it++) {
        __syncthreads();
        store_stage();
        __syncthreads();
        if (it + 1 < NI) load_stage((it + 1) * GBK);

#pragma unroll
        for (int ks = 0; ks < 2; ks++) {
            const int cb = ks * 2;
            uint32_t ah[4][4], bh[4][2], bl[4][2];

#pragma unroll
            for (int mt = 0; mt < 4; mt++) {
                int r = wm + mt * 16 + a_r;
                uint32_t ad = sAh + r * 64 + (((cb + a_c) ^ ((r >> 1) & 3)) << 4);
                LDSM4(ah[mt][0], ah[mt][1], ah[mt][2], ah[mt][3], ad);
            }
#pragma unroll
            for (int np = 0; np < 2; np++) {
                int r = wn + np * 16 + b_r;
                uint32_t bd = sBh + r * 64 + (((cb + b_c) ^ ((r >> 1) & 3)) << 4);
                LDSM4(bh[2 * np][0], bh[2 * np][1], bh[2 * np + 1][0], bh[2 * np + 1][1], bd);
            }
#pragma unroll
            for (int mt = 0; mt < 4; mt++)
#pragma unroll
                for (int nt = 0; nt < 4; nt++)
                    MMA16816(acc[mt][nt], ah[mt][0], ah[mt][1], ah[mt][2], ah[mt][3],
                             bh[nt][0], bh[nt][1]);
#pragma unroll
            for (int np = 0; np < 2; np++) {
                int r = wn + np * 16 + b_r;
                uint32_t bd = sBl + r * 64 + (((cb + b_c) ^ ((r >> 1) & 3)) << 4);
                LDSM4(bl[2 * np][0], bl[2 * np][1], bl[2 * np + 1][0], bl[2 * np + 1][1], bd);
            }
#pragma unroll
            for (int mt = 0; mt < 4; mt++)
#pragma unroll
                for (int nt = 0; nt < 4; nt++)
                    MMA16816(acc[mt][nt], ah[mt][0], ah[mt][1], ah[mt][2], ah[mt][3],
                             bl[nt][0], bl[nt][1]);
#pragma unroll
            for (int mt = 0; mt < 4; mt++) {
                int r = wm + mt * 16 + a_r;
                uint32_t ad = sAl + r * 64 + (((cb + a_c) ^ ((r >> 1) & 3)) << 4);
                LDSM4(ah[mt][0], ah[mt][1], ah[mt][2], ah[mt][3], ad);
            }
#pragma unroll
            for (int mt = 0; mt < 4; mt++)
#pragma unroll
                for (int nt = 0; nt < 4; nt++)
                    MMA16816(acc[mt][nt], ah[mt][0], ah[mt][1], ah[mt][2], ah[mt][3],
                             bh[nt][0], bh[nt][1]);
        }
    }

    const int lr = lane >> 2;
    const int lc = (lane & 3) * 2;
#pragma unroll
    for (int mt = 0; mt < 4; mt++) {
#pragma unroll
        for (int nt = 0; nt < 4; nt++) {
            float* p = C + (size_t)(m0 + wm + mt * 16 + lr) * N + n0 + wn + nt * 8 + lc;
            *(float2*)p             = make_float2(acc[mt][nt][0], acc[mt][nt][1]);
            *(float2*)(p + 8 * N)   = make_float2(acc[mt][nt][2], acc[mt][nt][3]);
        }
    }
}

// ---------------------------------------------------------------------------
// RoPE, in place on q (S x 2048) and k (S x 1024).
// ---------------------------------------------------------------------------
__global__ void rope_kernel(float* __restrict__ q, float* __restrict__ k,
                            const int* __restrict__ pos)
{
    const int TQ = S_LEN * NH_Q * 128;
    const int TK = S_LEN * N_KV * 128;
    int i = blockIdx.x * blockDim.x + threadIdx.x;
    if (i >= TQ + TK) return;

    float* base;
    int s, d;
    if (i < TQ) {
        d = i & 127;
        int h = (i >> 7) & 7;
        s = i >> 10;
        base = q + (size_t)s * QO_W + h * HD_H;
    } else {
        int j = i - TQ;
        d = j & 127;
        int h = (j >> 7) & 3;
        s = j >> 9;
        base = k + (size_t)s * KV_W + h * HD_H;
    }
    float p   = (float)pos[s];
    float inv = powf(10000.f, -(float)d * (1.f / 128.f));
    float ang = p * inv;
    float c, sn;
    sincosf(ang, &sn, &c);
    float x1 = base[d];
    float x2 = base[d + 128];
    base[d]       = x1 * c - x2 * sn;
    base[d + 128] = x2 * c + x1 * sn;
}

// ===========================================================================
// Flash attention on HMMA (bf16x3 split for QK^T and P*V).
// BM=BN=64, HD=256, 256 threads. Warp grid: wr=wid>>1 (16 rows), wc=wid&1.
// Smem (dynamic, ~179KB, 1 CTA/SM): Q hi/lo resident, V hi/lo tile-wide,
// K hi/lo streamed in 64-dim chunks, P hi/lo bf16, Ps fp32 scratch.
// Swizzle: 16B-chunk index ^ (row & 7); all row strides multiple of 128B.
// ===========================================================================
#define AOFF_QH  0
#define AOFF_QL  32768
#define AOFF_VH  65536
#define AOFF_VL  98304
#define AOFF_KH  131072
#define AOFF_KL  139264
#define AOFF_PBH 147456
#define AOFF_PBL 155648
#define AOFF_PS  163840
#define AOFF_MS  181248
#define AOFF_LS  181504
#define AOFF_SF  181760
#define AOFF_RED 182016
#define ATTN_SMEM_BYTES (183040 + 128)

__global__ void __launch_bounds__(256) attn_mma(
    const float* __restrict__ qg, const float* __restrict__ kg,
    const float* __restrict__ vg, float* __restrict__ outg)
{
    extern __shared__ unsigned char asm_raw[];
    uint32_t sb = smem_u32(asm_raw);
    sb = (sb + 127u) & ~127u;

    const uint32_t sQh = sb + AOFF_QH,  sQl = sb + AOFF_QL;
    const uint32_t sVh = sb + AOFF_VH,  sVl = sb + AOFF_VL;
    const uint32_t sKh = sb + AOFF_KH,  sKl = sb + AOFF_KL;
    const uint32_t sPh = sb + AOFF_PBH, sPl = sb + AOFF_PBL;
    float* Ps  = (float*)(asm_raw + (sb - smem_u32(asm_raw)) + AOFF_PS);
    float* m_s = (float*)(asm_raw + (sb - smem_u32(asm_raw)) + AOFF_MS);
    float* l_s = (float*)(asm_raw + (sb - smem_u32(asm_raw)) + AOFF_LS);
    float* sf_s= (float*)(asm_raw + (sb - smem_u32(asm_raw)) + AOFF_SF);
    float* red = (float*)(asm_raw + (sb - smem_u32(asm_raw)) + AOFF_RED);

    const int tid  = threadIdx.x;
    const int wid  = tid >> 5;
    const int lane = tid & 31;
    const int wr   = wid >> 1;          // 0..3 -> 16 q-rows
    const int wc   = wid & 1;           // 0..1 -> col half
    const int qt   = gridDim.x - 1 - blockIdx.x;   // heavy tiles first
    const int h    = blockIdx.y;
    const int qs   = qt * 64;
    const int kvh  = h >> 1;
    const float SCALE_F = 0.0625f;
    const float CAP = 50.f, INV_CAP2 = 2.f / 50.f;

    const int a_r = (lane & 7) + ((lane >> 3) & 1) * 8;
    const int a_c = (lane >> 4) & 1;
    const int b_r = (lane & 7) + ((lane >> 4) & 1) * 8;
    const int b_c = (lane >> 3) & 1;
    const int lr  = lane >> 2;
    const int lc  = (lane & 3) * 2;

    // ---- load + scale + split Q (64 x 256) ----
    {
        const float* qbase = qg + (size_t)qs * QO_W + h * HD_H;
#pragma unroll
        for (int i = 0; i < 16; i++) {
            int idx = tid + i * 256;
            int r = idx >> 6, c4 = idx & 63;
            float4 v = *(const float4*)(qbase + (size_t)r * QO_W + c4 * 4);
            v.x *= SCALE_F; v.y *= SCALE_F; v.z *= SCALE_F; v.w *= SCALE_F;
            uint32_t off = r * 512 + ((((c4 >> 1)) ^ (r & 7)) << 4) + (c4 & 1) * 8;
            cvt_store(sQh + off, sQl + off, v);
        }
    }
    if (tid < 64) { m_s[tid] = -1e30f; l_s[tid] = 0.f; }

    // O accumulator: per warp rows wr*16..+16, dims wc*128..+128 -> 16 n8 tiles
    float o[16][4];
#pragma unroll
    for (int nt = 0; nt < 16; nt++)
#pragma unroll
        for (int q = 0; q < 4; q++) o[nt][q] = 0.f;

    const int kt_lo = (qs - (SWIN - 1) > 0 ? qs - (SWIN - 1) : 0) >> 6;
    const float* kb0 = kg + kvh * HD_H;
    const float* vb0 = vg + kvh * HD_H;

    float4 stK[4], stV[4];
    auto stage = [&](const float* kbase, const float* vbase, int dc) {
#pragma unroll
        for (int i = 0; i < 4; i++) {
            int idx = tid + i * 256;
            int r = idx >> 4, c4 = idx & 15;
            stK[i] = *(const float4*)(kbase + (size_t)r * KV_W + dc * 64 + c4 * 4);
            stV[i] = *(const float4*)(vbase + (size_t)r * KV_W + dc * 64 + c4 * 4);
        }
    };

    for (int kt = qt; kt >= kt_lo; kt--) {
        const int ks0 = kt * 64;
        const float* kbase = kb0 + (size_t)ks0 * KV_W;
        const float* vbase = vb0 + (size_t)ks0 * KV_W;

        float s[4][4];
#pragma unroll
        for (int nt = 0; nt < 4; nt++)
#pragma unroll
            for (int q = 0; q < 4; q++) s[nt][q] = 0.f;

        stage(kbase, vbase, 0);

        // ---- QK^T over 4 d-chunks of 64 ----
        for (int dc = 0; dc < 4; dc++) {
            __syncthreads();   // prev consumers of K/V smem done
            // store K chunk (per-chunk tile) + V quarter (into full V tile)
#pragma unroll
            for (int i = 0; i < 4; i++) {
                int idx = tid + i * 256;
                int r = idx >> 4, c4 = idx & 15;
                uint32_t offk = r * 128 + ((((c4 >> 1)) ^ (r & 7)) << 4) + (c4 & 1) * 8;
                cvt_store(sKh + offk, sKl + offk, stK[i]);
                uint32_t offv = r * 512 + (((dc * 8 + (c4 >> 1)) ^ (r & 7)) << 4) + (c4 & 1) * 8;
                cvt_store(sVh + offv, sVl + offv, stV[i]);
            }
            __syncthreads();
            if (dc < 3) stage(kbase, vbase, dc + 1);

#pragma unroll
            for (int ks = 0; ks < 4; ks++) {
                const int cbq = dc * 8 + ks * 2;   // Q chunk base
                const int cbk = ks * 2;            // K chunk-local base
                uint32_t ah[4], al[4], bh[2][4], bl[4];
                {
                    int r = wr * 16 + a_r;
                    uint32_t adh = sQh + r * 512 + (((cbq + a_c) ^ (r & 7)) << 4);
                    uint32_t adl = sQl + r * 512 + (((cbq + a_c) ^ (r & 7)) << 4);
                    LDSM4(ah[0], ah[1], ah[2], ah[3], adh);
                    LDSM4(al[0], al[1], al[2], al[3], adl);
                }
#pragma unroll
                for (int np = 0; np < 2; np++) {
                    int r = wc * 32 + np * 16 + b_r;
                    uint32_t bd = sKh + r * 128 + (((cbk + b_c) ^ (r & 7)) << 4);
                    LDSM4(bh[np][0], bh[np][1], bh[np][2], bh[np][3], bd);
                }
#pragma unroll
                for (int np = 0; np < 2; np++) {
                    MMA16816(s[2 * np],     ah[0], ah[1], ah[2], ah[3], bh[np][0], bh[np][1]);
                    MMA16816(s[2 * np + 1], ah[0], ah[1], ah[2], ah[3], bh[np][2], bh[np][3]);
                    MMA16816(s[2 * np],     al[0], al[1], al[2], al[3], bh[np][0], bh[np][1]);
                    MMA16816(s[2 * np + 1], al[0], al[1], al[2], al[3], bh[np][2], bh[np][3]);
                }
#pragma unroll
                for (int np = 0; np < 2; np++) {
                    int r = wc * 32 + np * 16 + b_r;
                    uint32_t bd = sKl + r * 128 + (((cbk + b_c) ^ (r & 7)) << 4);
                    LDSM4(bl[0], bl[1], bl[2], bl[3], bd);
                    MMA16816(s[2 * np],     ah[0], ah[1], ah[2], ah[3], bl[0], bl[1]);
                    MMA16816(s[2 * np + 1], ah[0], ah[1], ah[2], ah[3], bl[2], bl[3]);
                }
            }
        }

        // ---- softcap + mask -> Ps ----
#pragma unroll
        for (int nt = 0; nt < 4; nt++) {
            int col = wc * 32 + nt * 8 + lc;
            int gj0 = ks0 + col;
#pragma unroll
            for (int half = 0; half < 2; half++) {
                int row = wr * 16 + lr + half * 8;
                int gi = qs + row;
                float t0 = __expf(s[nt][2 * half + 0] * INV_CAP2);
                float t1 = __expf(s[nt][2 * half + 1] * INV_CAP2);
                float sv0 = CAP - __fdividef(2.f * CAP, t0 + 1.f);
                float sv1 = CAP - __fdividef(2.f * CAP, t1 + 1.f);
                bool ok0 = (gj0 <= gi)     && ((gi - gj0) < SWIN);
                bool ok1 = (gj0 + 1 <= gi) && ((gi - gj0 - 1) < SWIN);
                *(float2*)&Ps[row * 68 + col] =
                    make_float2(ok0 ? sv0 : -1e30f, ok1 ? sv1 : -1e30f);
            }
        }
        __syncthreads();

        // ---- row max ----
        {
            int row = tid >> 2, l4 = tid & 3;
            const float* pr = Ps + row * 68 + l4 * 16;
            float mx = -1e30f;
#pragma unroll
            for (int t = 0; t < 16; t++) mx = fmaxf(mx, pr[t]);
            red[row * 4 + l4] = mx;
        }
        __syncthreads();
        if (tid < 64) {
            float mt = fmaxf(fmaxf(red[tid * 4], red[tid * 4 + 1]),
                             fmaxf(red[tid * 4 + 2], red[tid * 4 + 3]));
            float mo = m_s[tid];
            float mn = fmaxf(mo, mt);
            sf_s[tid] = __expf(mo - mn);
            m_s[tid]  = mn;
        }
        __syncthreads();

        // ---- exp -> P bf16 hi/lo + row sums ----
        {
            int row = tid >> 2, l4 = tid & 3;
            float mn = m_s[row];
            const float* pr = Ps + row * 68 + l4 * 16;
            float sum = 0.f;
#pragma unroll
            for (int g = 0; g < 4; g++) {
                float e[4];
#pragma unroll
                for (int t = 0; t < 4; t++) {
                    float pv = pr[g * 4 + t];
                    e[t] = (pv < -1e29f) ? 0.f : __expf(pv - mn);
                    sum += e[t];
                }
                uint32_t chunk = l4 * 2 + (g >> 1);
                uint32_t off = row * 128 + ((chunk ^ (row & 7)) << 4) + (g & 1) * 8;
                cvt_store(sPh + off, sPl + off, make_float4(e[0], e[1], e[2], e[3]));
            }
            red[row * 4 + l4] = sum;
        }
        __syncthreads();
        if (tid < 64) {
            l_s[tid] = l_s[tid] * sf_s[tid] +
                       (red[tid * 4] + red[tid * 4 + 1] +
                        red[tid * 4 + 2] + red[tid * 4 + 3]);
        }

        // ---- rescale O ----
        {
            float sfa = sf_s[wr * 16 + lr];
            float sfb = sf_s[wr * 16 + lr + 8];
#pragma unroll
            for (int nt = 0; nt < 16; nt++) {
                o[nt][0] *= sfa; o[nt][1] *= sfa;
                o[nt][2] *= sfb; o[nt][3] *= sfb;
            }
        }

        // ---- O += P V  (keys 64 = 4 k-steps; warp dims wc*128..+128) ----
#pragma unroll
        for (int kk = 0; kk < 4; kk++) {
            uint32_t ah[4], al[4];
            {
                int r = wr * 16 + a_r;
                uint32_t c = kk * 2 + a_c;
                LDSM4(ah[0], ah[1], ah[2], ah[3], sPh + r * 128 + ((c ^ (r & 7)) << 4));
                LDSM4(al[0], al[1], al[2], al[3], sPl + r * 128 + ((c ^ (r & 7)) << 4));
            }
#pragma unroll
            for (int vp = 0; vp < 8; vp++) {
                int key = kk * 16 + a_r;                     // bit3 -> +8 keys
                uint32_t chv = wc * 16 + vp * 2 + a_c;       // bit4 -> +8 dims
                uint32_t vb[4], vl[4];
                LDSM4T(vb[0], vb[1], vb[2], vb[3],
                       sVh + key * 512 + ((chv ^ (key & 7)) << 4));
                MMA16816(o[2 * vp],     ah[0], ah[1], ah[2], ah[3], vb[0], vb[1]);
                MMA16816(o[2 * vp + 1], ah[0], ah[1], ah[2], ah[3], vb[2], vb[3]);
                MMA16816(o[2 * vp],     al[0], al[1], al[2], al[3], vb[0], vb[1]);
                MMA16816(o[2 * vp + 1], al[0], al[1], al[2], al[3], vb[2], vb[3]);
                LDSM4T(vl[0], vl[1], vl[2], vl[3],
                       sVl + key * 512 + ((chv ^ (key & 7)) << 4));
                MMA16816(o[2 * vp],     ah[0], ah[1], ah[2], ah[3], vl[0], vl[1]);
                MMA16816(o[2 * vp + 1], ah[0], ah[1], ah[2], ah[3], vl[2], vl[3]);
            }
        }
    }

    __syncthreads();
    // ---- normalize + write out ----
    {
        float inva = 1.f / l_s[wr * 16 + lr];
        float invb = 1.f / l_s[wr * 16 + lr + 8];
        float* op0 = outg + (size_t)(qs + wr * 16 + lr) * QO_W + h * HD_H + wc * 128;
        float* op1 = op0 + 8 * QO_W;
#pragma unroll
        for (int nt = 0; nt < 16; nt++) {
            *(float2*)(op0 + nt * 8 + lc) = make_float2(o[nt][0] * inva, o[nt][1] * inva);
            *(float2*)(op1 + nt * 8 + lc) = make_float2(o[nt][2] * invb, o[nt][3] * invb);
        }
    }
}

// ---------------------------------------------------------------------------
// Launch
// ---------------------------------------------------------------------------
extern "C" void kernel_launch(void* const* d_in, const int* in_sizes, int n_in,
                              void* d_out, int out_size)
{
    const float* x   = (const float*)d_in[0];   // [4096, 2304]
    const int*   pos = (const int*)  d_in[1];   // [1, 4096]
    const float* Wq  = (const float*)d_in[2];   // [2048, 2304]
    const float* Wk  = (const float*)d_in[3];   // [1024, 2304]
    const float* Wv  = (const float*)d_in[4];   // [1024, 2304]
    const float* Wo  = (const float*)d_in[5];   // [2304, 2048]
    float* out = (float*)d_out;                 // [4096, 2304]

    float *gq, *gk, *gv, *gao;
    cudaGetSymbolAddress((void**)&gq,  g_q);
    cudaGetSymbolAddress((void**)&gk,  g_k);
    cudaGetSymbolAddress((void**)&gv,  g_v);
    cudaGetSymbolAddress((void**)&gao, g_ao);

    cudaFuncSetAttribute(attn_mma, cudaFuncAttributeMaxDynamicSharedMemorySize,
                         ATTN_SMEM_BYTES);

    // QKV projections on HMMA (bf16x3 split): C = A * W^T
    gemm_mma<<<dim3(QO_W / 128, S_LEN / 128), 256>>>(x, Wq, gq, QO_W, HID_D);
    gemm_mma<<<dim3(KV_W / 128, S_LEN / 128), 256>>>(x, Wk, gk, KV_W, HID_D);
    gemm_mma<<<dim3(KV_W / 128, S_LEN / 128), 256>>>(x, Wv, gv, KV_W, HID_D);

    // RoPE in place on q and k
    {
        int total = S_LEN * (NH_Q + N_KV) * 128;
        rope_kernel<<<(total + 255) / 256, 256>>>(gq, gk, pos);
    }

    // Flash attention on HMMA
    attn_mma<<<dim3(S_LEN / 64, NH_Q), 256, ATTN_SMEM_BYTES>>>(gq, gk, gv, gao);

    // Output projection: out = AO * Wo^T
    gemm_mma<<<dim3(HID_D / 128, S_LEN / 128), 256>>>(gao, Wo, out, HID_D, QO_W);
}